// round 1
// baseline (speedup 1.0000x reference)
#include <cuda_runtime.h>
#include <cuda_bf16.h>
#include <math.h>
#include <stdint.h>

// Problem constants
#define BB 16
#define SS 1024
#define EE 256
#define HH 256
#define FH 512
#define VV 8000
#define WSZ 5
#define NPOS (BB*SS)            // 16384

// ---------------- device scratch (no cudaMalloc allowed) ----------------
__device__ __nv_bfloat16 g_embB[VV*EE];            // embed table bf16, row0 zeroed
__device__ __nv_bfloat16 g_WihB[2*1024*256];       // gate-interleaved rows
__device__ __nv_bfloat16 g_WhhB[2*1024*256];       // gate-interleaved rows
__device__ float         g_bias[2*1024];           // bih+bhh, interleaved
__device__ __nv_bfloat16 g_fc1B[512*512];
__device__ float         g_prj [2u*NPOS*1024];     // input projections (fp32, 128MB)
__device__ float         g_c   [2u*NPOS*256];      // LSTM cell state fp32
__device__ __nv_bfloat16 g_h   [2][2u*NPOS*256];   // [parity][dir*n*u] h state bf16
__device__ __nv_bfloat16 g_hcat[ (size_t)NPOS*512];// leaky(concat(h_f,h_b)) bf16
__device__ __nv_bfloat16 g_fc1o[ (size_t)NPOS*512];// leaky(fc1 out) bf16

// ---------------- small helpers ----------------
__device__ __forceinline__ float sigm(float x){ return 1.f/(1.f+expf(-x)); }
__device__ __forceinline__ float lrelu(float x){ return x>0.f? x : 0.01f*x; }

__device__ __forceinline__ void ldm_x4(uint32_t&r0,uint32_t&r1,uint32_t&r2,uint32_t&r3,const void*p){
    uint32_t a=(uint32_t)__cvta_generic_to_shared(p);
    asm volatile("ldmatrix.sync.aligned.m8n8.x4.shared.b16 {%0,%1,%2,%3},[%4];\n"
        :"=r"(r0),"=r"(r1),"=r"(r2),"=r"(r3):"r"(a));
}
__device__ __forceinline__ void ldm_x2(uint32_t&r0,uint32_t&r1,const void*p){
    uint32_t a=(uint32_t)__cvta_generic_to_shared(p);
    asm volatile("ldmatrix.sync.aligned.m8n8.x2.shared.b16 {%0,%1},[%2];\n"
        :"=r"(r0),"=r"(r1):"r"(a));
}
__device__ __forceinline__ void mma_bf16(float*c,const uint32_t*a,const uint32_t*b){
    asm volatile("mma.sync.aligned.m16n8k16.row.col.f32.bf16.bf16.f32 "
        "{%0,%1,%2,%3},{%4,%5,%6,%7},{%8,%9},{%0,%1,%2,%3};\n"
        :"+f"(c[0]),"+f"(c[1]),"+f"(c[2]),"+f"(c[3])
        :"r"(a[0]),"r"(a[1]),"r"(a[2]),"r"(a[3]),"r"(b[0]),"r"(b[1]));
}

// ---------------- prep: bf16 casts + gate interleave permutation ----------------
__global__ void prep_kernel(const float*__restrict__ embed,
                            const float*__restrict__ Wih_f,const float*__restrict__ Whh_f,
                            const float*__restrict__ bih_f,const float*__restrict__ bhh_f,
                            const float*__restrict__ Wih_b,const float*__restrict__ Whh_b,
                            const float*__restrict__ bih_b,const float*__restrict__ bhh_b,
                            const float*__restrict__ fc1_w)
{
    int idx = blockIdx.x*blockDim.x + threadIdx.x;
    if (idx < VV*EE) g_embB[idx] = __float2bfloat16(idx < EE ? 0.f : embed[idx]); // row 0 zeroed
    if (idx < 1024*256) {
        int jp = idx>>8, e = idx&255;
        int u = jp>>2, g = jp&3;                 // interleaved col 4u+g  <-  orig row g*256+u
        int src = (g*256+u)*256 + e;
        g_WihB[idx]            = __float2bfloat16(Wih_f[src]);
        g_WihB[1024*256 + idx] = __float2bfloat16(Wih_b[src]);
        g_WhhB[idx]            = __float2bfloat16(Whh_f[src]);
        g_WhhB[1024*256 + idx] = __float2bfloat16(Whh_b[src]);
        g_fc1B[idx]            = __float2bfloat16(fc1_w[idx]);   // no permutation
    }
    if (idx < 1024) {
        int u = idx>>2, g = idx&3; int s = g*256+u;
        g_bias[idx]        = bih_f[s] + bhh_f[s];
        g_bias[1024 + idx] = bih_b[s] + bhh_b[s];
    }
}

// ---------------- shared bf16 MMA GEMM core, 3 variants ----------------
// C(M=16384, N) = A(M,K) * B(N,K)^T ; CTA tile 128x64, BK=64, 4 warps (warp tile 64x32)
enum { MODE_PROJ = 0, MODE_STEP = 1, MODE_FC1 = 2 };

template<int MODE>
__global__ void __launch_bounds__(128)
gemm_kernel(const int*__restrict__ xtok, const float*__restrict__ fc1_b, int kstep)
{
    constexpr int Kdim = (MODE==MODE_FC1) ? 512 : 256;
    const int tileN = blockIdx.x;
    const int n0    = blockIdx.y * 128;
    const int z     = blockIdx.z;               // direction (0 fwd / 1 bwd); 0 for FC1
    const int tid   = threadIdx.x;
    const int warp  = tid>>5, lane = tid&31;
    const int wm    = warp>>1, wn = warp&1;

    __shared__ __align__(16) unsigned char raw[35328];
    __nv_bfloat16 (*As)[72] = (__nv_bfloat16(*)[72])raw;                 // 128x72 bf16
    __nv_bfloat16 (*Bs)[72] = (__nv_bfloat16(*)[72])(raw + 18432);       //  64x72 bf16
    float         (*Cs)[68] = (float(*)[68])raw;                          // 128x68 f32 (aliased)
    int* tokS = (int*)(raw + 34816);

    const __nv_bfloat16* Bglob;
    if      (MODE==MODE_PROJ) Bglob = g_WihB + (size_t)z*1024*256;
    else if (MODE==MODE_STEP) Bglob = g_WhhB + (size_t)z*1024*256;
    else                      Bglob = g_fc1B;

    const __nv_bfloat16* Abase = nullptr;
    if (MODE==MODE_STEP) Abase = g_h[(kstep+1)&1] + (size_t)z*NPOS*256;
    if (MODE==MODE_FC1)  Abase = g_hcat;

    if (MODE==MODE_PROJ) { tokS[tid] = xtok[n0 + tid]; __syncthreads(); }

    float acc[4][4][4];
    #pragma unroll
    for (int a=0;a<4;a++) for (int b=0;b<4;b++) for (int c=0;c<4;c++) acc[a][b][c]=0.f;

    for (int kt = 0; kt < Kdim/64; kt++) {
        const int k0 = kt*64;
        #pragma unroll
        for (int i=0;i<8;i++) {                       // A tile 128x64
            int idx = i*128 + tid; int r = idx>>3; int c = (idx&7)*8;
            const __nv_bfloat16* src;
            if (MODE==MODE_PROJ) src = g_embB + (size_t)tokS[r]*EE + k0 + c;
            else                 src = Abase + (size_t)(n0+r)*Kdim + k0 + c;
            *(uint4*)&As[r][c] = *(const uint4*)src;
        }
        #pragma unroll
        for (int i=0;i<4;i++) {                       // B tile 64x64
            int idx = i*128 + tid; int r = idx>>3; int c = (idx&7)*8;
            *(uint4*)&Bs[r][c] = *(const uint4*)(Bglob + (size_t)(tileN*64 + r)*Kdim + k0 + c);
        }
        __syncthreads();
        #pragma unroll
        for (int kk=0; kk<4; kk++) {
            const int kb = kk*16;
            uint32_t afr[4][4], bfr[4][2];
            #pragma unroll
            for (int mi=0;mi<4;mi++)
                ldm_x4(afr[mi][0],afr[mi][1],afr[mi][2],afr[mi][3],
                       &As[wm*64 + mi*16 + (lane&15)][kb + (lane>>4)*8]);
            #pragma unroll
            for (int ni=0;ni<4;ni++)
                ldm_x2(bfr[ni][0],bfr[ni][1],
                       &Bs[wn*32 + ni*8 + (lane&7)][kb + ((lane>>3)&1)*8]);
            #pragma unroll
            for (int mi=0;mi<4;mi++)
                #pragma unroll
                for (int ni=0;ni<4;ni++)
                    mma_bf16(acc[mi][ni], afr[mi], bfr[ni]);
        }
        __syncthreads();
    }

    // ------------- epilogues -------------
    if (MODE==MODE_PROJ) {
        #pragma unroll
        for (int mi=0;mi<4;mi++)
        #pragma unroll
        for (int ni=0;ni<4;ni++) {
            int r = wm*64 + mi*16 + (lane>>2);
            int c = wn*32 + ni*8  + (lane&3)*2;
            size_t base = ((size_t)z*NPOS + (n0+r))*1024 + tileN*64 + c;
            *(float2*)&g_prj[base]        = make_float2(acc[mi][ni][0], acc[mi][ni][1]);
            *(float2*)&g_prj[base + 8192] = make_float2(acc[mi][ni][2], acc[mi][ni][3]); // (+8 rows)*1024
        }
    }
    else if (MODE==MODE_FC1) {
        #pragma unroll
        for (int mi=0;mi<4;mi++)
        #pragma unroll
        for (int ni=0;ni<4;ni++) {
            int r = wm*64 + mi*16 + (lane>>2);
            int c = tileN*64 + wn*32 + ni*8 + (lane&3)*2;
            float b0 = fc1_b[c], b1 = fc1_b[c+1];
            __nv_bfloat162 v0, v1;
            v0.x = __float2bfloat16(lrelu(acc[mi][ni][0] + b0));
            v0.y = __float2bfloat16(lrelu(acc[mi][ni][1] + b1));
            v1.x = __float2bfloat16(lrelu(acc[mi][ni][2] + b0));
            v1.y = __float2bfloat16(lrelu(acc[mi][ni][3] + b1));
            *(__nv_bfloat162*)&g_fc1o[(size_t)(n0+r)*512 + c]     = v0;
            *(__nv_bfloat162*)&g_fc1o[(size_t)(n0+r+8)*512 + c]   = v1;
        }
    }
    else { // MODE_STEP: stage gates in smem, fused LSTM update
        #pragma unroll
        for (int mi=0;mi<4;mi++)
        #pragma unroll
        for (int ni=0;ni<4;ni++) {
            int r = wm*64 + mi*16 + (lane>>2);
            int c = wn*32 + ni*8  + (lane&3)*2;
            Cs[r][c]     = acc[mi][ni][0];
            Cs[r][c+1]   = acc[mi][ni][1];
            Cs[r+8][c]   = acc[mi][ni][2];
            Cs[r+8][c+1] = acc[mi][ni][3];
        }
        __syncthreads();

        const int r  = tid;                 // one row (position) per thread
        const int n  = n0 + r;
        const int tp = n & (SS-1);
        const int sp = (z==0) ? (tp + kstep - WSZ) : (tp + WSZ - kstep);
        const bool valid = (z==0) ? (sp >= 0) : (sp < SS);
        const int nbr = n + (sp - tp);
        const size_t prjbase  = ((size_t)z*NPOS + nbr)*1024 + tileN*64;
        const size_t biasbase = (size_t)z*1024 + tileN*64;
        const size_t stbase   = ((size_t)z*NPOS + n)*256 + tileN*16;
        __nv_bfloat16* hout = g_h[kstep&1];

        #pragma unroll
        for (int u=0; u<16; u++) {
            float4 gv = *(const float4*)&Cs[r][u*4];
            float4 bv = *(const float4*)&g_bias[biasbase + u*4];
            gv.x += bv.x; gv.y += bv.y; gv.z += bv.z; gv.w += bv.w;
            if (valid) {
                float4 pv = *(const float4*)&g_prj[prjbase + u*4];
                gv.x += pv.x; gv.y += pv.y; gv.z += pv.z; gv.w += pv.w;
            }
            float gi = sigm(gv.x), gf = sigm(gv.y), gg = tanhf(gv.z), go = sigm(gv.w);
            float cold = g_c[stbase + u];
            float cnew = gf*cold + gi*gg;
            g_c[stbase + u] = cnew;
            hout[stbase + u] = __float2bfloat16(go * tanhf(cnew));
        }
    }
}

// ---------------- step 0: gates = valid?proj:0 + bias ; h=c=0 start ----------------
__global__ void step0_kernel()
{
    int idx = blockIdx.x*blockDim.x + threadIdx.x;   // 2*NPOS*256 total
    int u = idx & 255;
    int n = (idx >> 8) & (NPOS-1);
    int z = idx >> 22;
    int tp = n & (SS-1);
    int sp = (z==0) ? (tp - WSZ) : (tp + WSZ);
    bool valid = (z==0) ? (sp >= 0) : (sp < SS);
    int nbr = n + (sp - tp);
    float4 gv = make_float4(0.f,0.f,0.f,0.f);
    if (valid) gv = *(const float4*)&g_prj[((size_t)z*NPOS + nbr)*1024 + u*4];
    float4 bv = *(const float4*)&g_bias[(size_t)z*1024 + u*4];
    float gi = sigm(gv.x + bv.x);
    float gg = tanhf(gv.z + bv.z);
    float go = sigm(gv.w + bv.w);
    float c  = gi * gg;                 // f*c0 = 0
    g_c[idx]    = c;
    g_h[0][idx] = __float2bfloat16(go * tanhf(c));
}

// ---------------- concat + leaky ----------------
__global__ void concat_kernel()
{
    int idx = blockIdx.x*blockDim.x + threadIdx.x;   // NPOS*512
    int n = idx >> 9;
    int j = idx & 511;
    int z = j >> 8, u = j & 255;
    float v = __bfloat162float(g_h[1][(size_t)z*NPOS*256 + (size_t)n*256 + u]);
    g_hcat[idx] = __float2bfloat16(lrelu(v));
}

// ---------------- fc2 + sigmoid (warp per row) ----------------
__global__ void fc2_kernel(const float*__restrict__ w, const float*__restrict__ b,
                           float*__restrict__ out)
{
    int warp = threadIdx.x >> 5, lane = threadIdx.x & 31;
    int row = blockIdx.x*8 + warp;
    const __nv_bfloat16* a = g_fc1o + (size_t)row*512;
    float s = 0.f;
    #pragma unroll
    for (int i=0;i<16;i++) { int c = lane + i*32; s += __bfloat162float(a[c]) * w[c]; }
    #pragma unroll
    for (int off=16; off; off>>=1) s += __shfl_xor_sync(0xffffffffu, s, off);
    if (lane==0) out[row] = sigm(s + b[0]);
}

// ---------------- launch ----------------
extern "C" void kernel_launch(void* const* d_in, const int* in_sizes, int n_in,
                              void* d_out, int out_size)
{
    const int*   x      = (const int*)  d_in[0];
    const float* embed  = (const float*)d_in[1];
    const float* Wih_f  = (const float*)d_in[2];
    const float* Whh_f  = (const float*)d_in[3];
    const float* bih_f  = (const float*)d_in[4];
    const float* bhh_f  = (const float*)d_in[5];
    const float* Wih_b  = (const float*)d_in[6];
    const float* Whh_b  = (const float*)d_in[7];
    const float* bih_b  = (const float*)d_in[8];
    const float* bhh_b  = (const float*)d_in[9];
    const float* fc1_w  = (const float*)d_in[10];
    const float* fc1_b  = (const float*)d_in[11];
    const float* fc2_w  = (const float*)d_in[12];
    const float* fc2_b  = (const float*)d_in[13];
    float* out = (float*)d_out;

    prep_kernel<<<(VV*EE + 255)/256, 256>>>(embed, Wih_f, Whh_f, bih_f, bhh_f,
                                            Wih_b, Whh_b, bih_b, bhh_b, fc1_w);

    gemm_kernel<MODE_PROJ><<<dim3(16, NPOS/128, 2), 128>>>(x, nullptr, 0);

    step0_kernel<<<(2*NPOS*256)/256, 256>>>();

    for (int k = 1; k <= WSZ; k++)
        gemm_kernel<MODE_STEP><<<dim3(16, NPOS/128, 2), 128>>>(nullptr, nullptr, k);

    concat_kernel<<<(NPOS*512)/256, 256>>>();

    gemm_kernel<MODE_FC1><<<dim3(8, NPOS/128, 1), 128>>>(nullptr, fc1_b, 0);

    fc2_kernel<<<NPOS/8, 256>>>(fc2_w, fc2_b, out);
}

// round 3
// speedup vs baseline: 1.1248x; 1.1248x over previous
#include <cuda_runtime.h>
#include <cuda_bf16.h>
#include <math.h>
#include <stdint.h>

// Problem constants
#define BB 16
#define SS 1024
#define EE 256
#define HH 256
#define FH 512
#define VV 8000
#define WSZ 5
#define NPOS (BB*SS)            // 16384

// ---------------- device scratch (no cudaMalloc allowed) ----------------
__device__ __align__(16) __nv_bfloat16 g_embB[VV*EE];            // embed bf16, row0 zeroed
__device__ __align__(16) __nv_bfloat16 g_WihB[2*1024*256];       // gate-interleaved rows
__device__ __align__(16) __nv_bfloat16 g_WhhB[2*1024*256];       // gate-interleaved rows
__device__ __align__(16) float         g_bias[2*1024];           // bih+bhh, interleaved
__device__ __align__(16) __nv_bfloat16 g_fc1B[512*512];
__device__ __align__(16) __nv_bfloat16 g_prjB[2u*NPOS*1024];     // input projections bf16 (64MB)
__device__ __align__(16) float         g_c   [2u*NPOS*256];      // LSTM cell state fp32
__device__ __align__(16) __nv_bfloat16 g_h   [2][2u*NPOS*256];   // [parity][dir*n*u] h bf16
__device__ __align__(16) __nv_bfloat16 g_hcat[ (size_t)NPOS*512];// leaky(concat) bf16
__device__ __align__(16) __nv_bfloat16 g_fc1o[ (size_t)NPOS*512];// leaky(fc1 out) bf16

// ---------------- small helpers ----------------
__device__ __forceinline__ float sigm(float x){ return 1.f/(1.f+expf(-x)); }
__device__ __forceinline__ float lrelu(float x){ return x>0.f? x : 0.01f*x; }

__device__ __forceinline__ void ldm_x4(uint32_t&r0,uint32_t&r1,uint32_t&r2,uint32_t&r3,const void*p){
    uint32_t a=(uint32_t)__cvta_generic_to_shared(p);
    asm volatile("ldmatrix.sync.aligned.m8n8.x4.shared.b16 {%0,%1,%2,%3},[%4];\n"
        :"=r"(r0),"=r"(r1),"=r"(r2),"=r"(r3):"r"(a));
}
__device__ __forceinline__ void ldm_x2(uint32_t&r0,uint32_t&r1,const void*p){
    uint32_t a=(uint32_t)__cvta_generic_to_shared(p);
    asm volatile("ldmatrix.sync.aligned.m8n8.x2.shared.b16 {%0,%1},[%2];\n"
        :"=r"(r0),"=r"(r1):"r"(a));
}
__device__ __forceinline__ void mma_bf16(float*c,const uint32_t*a,const uint32_t*b){
    asm volatile("mma.sync.aligned.m16n8k16.row.col.f32.bf16.bf16.f32 "
        "{%0,%1,%2,%3},{%4,%5,%6,%7},{%8,%9},{%0,%1,%2,%3};\n"
        :"+f"(c[0]),"+f"(c[1]),"+f"(c[2]),"+f"(c[3])
        :"r"(a[0]),"r"(a[1]),"r"(a[2]),"r"(a[3]),"r"(b[0]),"r"(b[1]));
}
__device__ __forceinline__ void cpasync16(void* s, const void* g){
    uint32_t a=(uint32_t)__cvta_generic_to_shared(s);
    asm volatile("cp.async.cg.shared.global [%0],[%1],16;\n"::"r"(a),"l"(g));
}

// ---------------- prep: bf16 casts + gate interleave permutation ----------------
__global__ void prep_kernel(const float*__restrict__ embed,
                            const float*__restrict__ Wih_f,const float*__restrict__ Whh_f,
                            const float*__restrict__ bih_f,const float*__restrict__ bhh_f,
                            const float*__restrict__ Wih_b,const float*__restrict__ Whh_b,
                            const float*__restrict__ bih_b,const float*__restrict__ bhh_b,
                            const float*__restrict__ fc1_w)
{
    int idx = blockIdx.x*blockDim.x + threadIdx.x;
    if (idx < VV*EE) g_embB[idx] = __float2bfloat16(idx < EE ? 0.f : embed[idx]); // row 0 zeroed
    if (idx < 1024*256) {
        int jp = idx>>8, e = idx&255;
        int u = jp>>2, g = jp&3;                 // interleaved col 4u+g  <-  orig row g*256+u
        int src = (g*256+u)*256 + e;
        g_WihB[idx]            = __float2bfloat16(Wih_f[src]);
        g_WihB[1024*256 + idx] = __float2bfloat16(Wih_b[src]);
        g_WhhB[idx]            = __float2bfloat16(Whh_f[src]);
        g_WhhB[1024*256 + idx] = __float2bfloat16(Whh_b[src]);
        g_fc1B[idx]            = __float2bfloat16(fc1_w[idx]);   // no permutation
    }
    if (idx < 1024) {
        int u = idx>>2, g = idx&3; int s = g*256+u;
        g_bias[idx]        = bih_f[s] + bhh_f[s];
        g_bias[1024 + idx] = bih_b[s] + bhh_b[s];
    }
}

// ---------------- pipelined bf16 MMA GEMM core, 3 variants ----------------
// C(M=16384, N) = A(M,K) * B(N,K)^T
// CTA tile 128x128, BK=32, 2-stage cp.async pipeline, 8 warps (warp tile 64x32)
enum { MODE_PROJ = 0, MODE_STEP = 1, MODE_FC1 = 2 };

template<int MODE>
__global__ void __launch_bounds__(256,2)
gemm_kernel(const int*__restrict__ xtok, const float*__restrict__ fc1_b, int kstep)
{
    constexpr int Kdim = (MODE==MODE_FC1) ? 512 : 256;
    constexpr int KT   = Kdim/32;
    const int tileN = blockIdx.x;
    const int n0    = blockIdx.y * 128;
    const int z     = blockIdx.z;               // direction (0 fwd / 1 bwd); 0 for FC1
    const int tid   = threadIdx.x;
    const int warp  = tid>>5, lane = tid&31;
    const int wm    = warp>>2, wn = warp&3;     // 2 x 4 warp grid, warp tile 64x32

    __shared__ __align__(16) __nv_bfloat16 As[2][128][40];
    __shared__ __align__(16) __nv_bfloat16 Bs[2][128][40];
    __shared__ int tokS[128];

    const __nv_bfloat16* Bglob;
    if      (MODE==MODE_PROJ) Bglob = g_WihB + (size_t)z*1024*256;
    else if (MODE==MODE_STEP) Bglob = g_WhhB + (size_t)z*1024*256;
    else                      Bglob = g_fc1B;

    const __nv_bfloat16* Abase = nullptr;
    if (MODE==MODE_STEP) Abase = g_h[(kstep+1)&1] + (size_t)z*NPOS*256;
    if (MODE==MODE_FC1)  Abase = g_hcat;

    if (MODE==MODE_PROJ) {
        if (tid < 128) tokS[tid] = xtok[n0 + tid];
        __syncthreads();
    }

    const int nb0 = tileN*128;

    // stage loader: A tile 128x32, B tile 128x32, 16B chunks, 4 cp.async/thread
    auto load_stage = [&](int st, int kt){
        const int k0 = kt*32;
        #pragma unroll
        for (int i=0;i<2;i++) {
            int id = i*256 + tid; int r = id>>2; int c = (id&3)*8;
            const __nv_bfloat16* src;
            if (MODE==MODE_PROJ) src = g_embB + (size_t)tokS[r]*EE + k0 + c;
            else                 src = Abase + (size_t)(n0+r)*Kdim + k0 + c;
            cpasync16(&As[st][r][c], src);
        }
        #pragma unroll
        for (int i=0;i<2;i++) {
            int id = i*256 + tid; int r = id>>2; int c = (id&3)*8;
            cpasync16(&Bs[st][r][c], Bglob + (size_t)(nb0+r)*Kdim + k0 + c);
        }
    };

    float acc[4][4][4];
    #pragma unroll
    for (int a=0;a<4;a++) for (int b=0;b<4;b++) for (int c=0;c<4;c++) acc[a][b][c]=0.f;

    load_stage(0, 0);
    asm volatile("cp.async.commit_group;\n");

    for (int kt = 0; kt < KT; kt++) {
        if (kt+1 < KT) {
            load_stage((kt+1)&1, kt+1);
            asm volatile("cp.async.commit_group;\n");
            asm volatile("cp.async.wait_group 1;\n");
        } else {
            asm volatile("cp.async.wait_group 0;\n");
        }
        __syncthreads();
        const int st = kt&1;
        #pragma unroll
        for (int kk=0; kk<2; kk++) {
            const int kb = kk*16;
            uint32_t afr[4][4], bfr[4][2];
            #pragma unroll
            for (int mi=0;mi<4;mi++)
                ldm_x4(afr[mi][0],afr[mi][1],afr[mi][2],afr[mi][3],
                       &As[st][wm*64 + mi*16 + (lane&15)][kb + (lane>>4)*8]);
            #pragma unroll
            for (int ni=0;ni<4;ni++)
                ldm_x2(bfr[ni][0],bfr[ni][1],
                       &Bs[st][wn*32 + ni*8 + (lane&7)][kb + ((lane>>3)&1)*8]);
            #pragma unroll
            for (int mi=0;mi<4;mi++)
                #pragma unroll
                for (int ni=0;ni<4;ni++)
                    mma_bf16(acc[mi][ni], afr[mi], bfr[ni]);
        }
        __syncthreads();
    }

    // ------------- epilogues -------------
    if (MODE==MODE_PROJ) {
        #pragma unroll
        for (int mi=0;mi<4;mi++)
        #pragma unroll
        for (int ni=0;ni<4;ni++) {
            int r = wm*64 + mi*16 + (lane>>2);
            int gcol = tileN*128 + wn*32 + ni*8 + (lane&3)*2;
            __nv_bfloat162 v0, v1;
            v0.x = __float2bfloat16(acc[mi][ni][0]); v0.y = __float2bfloat16(acc[mi][ni][1]);
            v1.x = __float2bfloat16(acc[mi][ni][2]); v1.y = __float2bfloat16(acc[mi][ni][3]);
            *(__nv_bfloat162*)&g_prjB[((size_t)z*NPOS + (n0+r  ))*1024 + gcol] = v0;
            *(__nv_bfloat162*)&g_prjB[((size_t)z*NPOS + (n0+r+8))*1024 + gcol] = v1;
        }
    }
    else if (MODE==MODE_FC1) {
        #pragma unroll
        for (int mi=0;mi<4;mi++)
        #pragma unroll
        for (int ni=0;ni<4;ni++) {
            int r = wm*64 + mi*16 + (lane>>2);
            int c = tileN*128 + wn*32 + ni*8 + (lane&3)*2;
            float b0 = fc1_b[c], b1 = fc1_b[c+1];
            __nv_bfloat162 v0, v1;
            v0.x = __float2bfloat16(lrelu(acc[mi][ni][0] + b0));
            v0.y = __float2bfloat16(lrelu(acc[mi][ni][1] + b1));
            v1.x = __float2bfloat16(lrelu(acc[mi][ni][2] + b0));
            v1.y = __float2bfloat16(lrelu(acc[mi][ni][3] + b1));
            *(__nv_bfloat162*)&g_fc1o[(size_t)(n0+r  )*512 + c] = v0;
            *(__nv_bfloat162*)&g_fc1o[(size_t)(n0+r+8)*512 + c] = v1;
        }
    }
    else { // MODE_STEP: shuffle-fused LSTM update (lane pairs reunite i,f with g,o)
        const __nv_bfloat16* prjZ = g_prjB + (size_t)z*NPOS*1024;
        float*         cZ   = g_c + (size_t)z*NPOS*256;
        __nv_bfloat16* hout = g_h[kstep&1] + (size_t)z*NPOS*256;
        const float*   biasZ = g_bias + z*1024;
        #pragma unroll
        for (int mi=0;mi<4;mi++)
        #pragma unroll
        for (int ni=0;ni<4;ni++) {
            float a0=acc[mi][ni][0], a1=acc[mi][ni][1], a2=acc[mi][ni][2], a3=acc[mi][ni][3];
            float o0=__shfl_xor_sync(0xffffffffu,a0,1);
            float o1=__shfl_xor_sync(0xffffffffu,a1,1);
            float o2=__shfl_xor_sync(0xffffffffu,a2,1);
            float o3=__shfl_xor_sync(0xffffffffu,a3,1);
            if (!(lane&1)) {
                const int gcol = tileN*128 + wn*32 + ni*8 + ((lane&2)?4:0);
                const float4 bv = *(const float4*)&biasZ[gcol];
                const int ucol = gcol>>2;
                #pragma unroll
                for (int hrow=0; hrow<2; hrow++) {
                    const int n = n0 + wm*64 + mi*16 + (lane>>2) + hrow*8;
                    float gi_ = hrow? a2:a0, gf_ = hrow? a3:a1;
                    float gg_ = hrow? o2:o0, go_ = hrow? o3:o1;
                    const int tp = n & (SS-1);
                    const int sp = (z==0) ? (tp + kstep - WSZ) : (tp + WSZ - kstep);
                    const bool valid = (z==0) ? (sp >= 0) : (sp < SS);
                    if (valid) {
                        const int nbr = n + sp - tp;
                        const __nv_bfloat162* pp =
                            (const __nv_bfloat162*)&prjZ[(size_t)nbr*1024 + gcol];
                        float2 p0 = __bfloat1622float2(pp[0]);
                        float2 p1 = __bfloat1622float2(pp[1]);
                        gi_ += p0.x; gf_ += p0.y; gg_ += p1.x; go_ += p1.y;
                    }
                    gi_ += bv.x; gf_ += bv.y; gg_ += bv.z; go_ += bv.w;
                    float i_ = sigm(gi_), f_ = sigm(gf_), g_ = tanhf(gg_), oo = sigm(go_);
                    size_t st = (size_t)n*256 + ucol;
                    float cn = f_*cZ[st] + i_*g_;
                    cZ[st] = cn;
                    hout[st] = __float2bfloat16(oo * tanhf(cn));
                }
            }
        }
    }
}

// ---------------- step 0: gates = valid?proj:0 + bias ; h=c=0 start ----------------
__global__ void step0_kernel()
{
    int idx = blockIdx.x*blockDim.x + threadIdx.x;   // 2*NPOS*256 units
    int u = idx & 255;
    int n = (idx >> 8) & (NPOS-1);
    int z = idx >> 22;
    int tp = n & (SS-1);
    int sp = (z==0) ? (tp - WSZ) : (tp + WSZ);
    bool valid = (z==0) ? (sp >= 0) : (sp < SS);
    int nbr = n + (sp - tp);
    float4 gv = make_float4(0.f,0.f,0.f,0.f);
    if (valid) {
        const __nv_bfloat162* pp =
            (const __nv_bfloat162*)&g_prjB[((size_t)z*NPOS + nbr)*1024 + u*4];
        float2 p0 = __bfloat1622float2(pp[0]);
        float2 p1 = __bfloat1622float2(pp[1]);
        gv = make_float4(p0.x, p0.y, p1.x, p1.y);
    }
    float4 bv = *(const float4*)&g_bias[(size_t)z*1024 + u*4];
    float gi = sigm(gv.x + bv.x);
    float gg = tanhf(gv.z + bv.z);
    float go = sigm(gv.w + bv.w);
    float c  = gi * gg;                 // f*c0 = 0
    g_c[idx]    = c;
    g_h[0][idx] = __float2bfloat16(go * tanhf(c));
}

// ---------------- concat + leaky ----------------
__global__ void concat_kernel()
{
    int idx = blockIdx.x*blockDim.x + threadIdx.x;   // NPOS*512
    int n = idx >> 9;
    int j = idx & 511;
    int z = j >> 8, u = j & 255;
    float v = __bfloat162float(g_h[1][(size_t)z*NPOS*256 + (size_t)n*256 + u]);
    g_hcat[idx] = __float2bfloat16(lrelu(v));
}

// ---------------- fc2 + sigmoid (warp per row) ----------------
__global__ void fc2_kernel(const float*__restrict__ w, const float*__restrict__ b,
                           float*__restrict__ out)
{
    int warp = threadIdx.x >> 5, lane = threadIdx.x & 31;
    int row = blockIdx.x*8 + warp;
    const __nv_bfloat16* a = g_fc1o + (size_t)row*512;
    float s = 0.f;
    #pragma unroll
    for (int i=0;i<16;i++) { int c = lane + i*32; s += __bfloat162float(a[c]) * w[c]; }
    #pragma unroll
    for (int off=16; off; off>>=1) s += __shfl_xor_sync(0xffffffffu, s, off);
    if (lane==0) out[row] = sigm(s + b[0]);
}

// ---------------- launch ----------------
extern "C" void kernel_launch(void* const* d_in, const int* in_sizes, int n_in,
                              void* d_out, int out_size)
{
    const int*   x      = (const int*)  d_in[0];
    const float* embed  = (const float*)d_in[1];
    const float* Wih_f  = (const float*)d_in[2];
    const float* Whh_f  = (const float*)d_in[3];
    const float* bih_f  = (const float*)d_in[4];
    const float* bhh_f  = (const float*)d_in[5];
    const float* Wih_b  = (const float*)d_in[6];
    const float* Whh_b  = (const float*)d_in[7];
    const float* bih_b  = (const float*)d_in[8];
    const float* bhh_b  = (const float*)d_in[9];
    const float* fc1_w  = (const float*)d_in[10];
    const float* fc1_b  = (const float*)d_in[11];
    const float* fc2_w  = (const float*)d_in[12];
    const float* fc2_b  = (const float*)d_in[13];
    float* out = (float*)d_out;

    prep_kernel<<<(VV*EE + 255)/256, 256>>>(embed, Wih_f, Whh_f, bih_f, bhh_f,
                                            Wih_b, Whh_b, bih_b, bhh_b, fc1_w);

    gemm_kernel<MODE_PROJ><<<dim3(8, NPOS/128, 2), 256>>>(x, nullptr, 0);

    step0_kernel<<<(2*NPOS*256)/256, 256>>>();

    for (int k = 1; k <= WSZ; k++)
        gemm_kernel<MODE_STEP><<<dim3(8, NPOS/128, 2), 256>>>(nullptr, nullptr, k);

    concat_kernel<<<(NPOS*512)/256, 256>>>();

    gemm_kernel<MODE_FC1><<<dim3(4, NPOS/128, 1), 256>>>(nullptr, fc1_b, 0);

    fc2_kernel<<<NPOS/8, 256>>>(fc2_w, fc2_b, out);
}

// round 13
// speedup vs baseline: 1.1524x; 1.0245x over previous
#include <cuda_runtime.h>
#include <cuda_bf16.h>
#include <math.h>
#include <stdint.h>

// Problem constants
#define BB 16
#define SS 1024
#define EE 256
#define HH 256
#define FH 512
#define VV 8000
#define WSZ 5
#define NPOS (BB*SS)            // 16384

// NOTE: harness builds PTX at compute_103 (no 'a'): tcgen05/TMEM are ptxas-rejected.
// Legal fast path = mma.sync HMMA + cp.async + ldmatrix. This kernel optimizes that path.

// ---------------- device scratch (no cudaMalloc allowed) ----------------
__device__ __align__(16) __nv_bfloat16 g_embB[VV*EE];            // embed bf16, row0 zeroed
__device__ __align__(16) __nv_bfloat16 g_WihB[2*1024*256];       // gate-interleaved rows
__device__ __align__(16) __nv_bfloat16 g_WhhB[2*1024*256];       // gate-interleaved rows
__device__ __align__(16) float         g_bias[2*1024];           // bih+bhh, interleaved
__device__ __align__(16) __nv_bfloat16 g_fc1B[512*512];
__device__ __align__(16) __nv_bfloat16 g_prjB[2u*NPOS*1024];     // input projections bf16 (64MB)
__device__ __align__(16) float         g_c   [2u*NPOS*256];      // LSTM cell state fp32
__device__ __align__(16) __nv_bfloat16 g_h   [2][2u*NPOS*256];   // [parity][dir*n*u] h bf16
__device__ __align__(16) __nv_bfloat16 g_hcat[ (size_t)NPOS*512];// leaky(concat) bf16
__device__ __align__(16) __nv_bfloat16 g_fc1o[ (size_t)NPOS*512];// leaky(fc1 out) bf16

// ---------------- small helpers ----------------
__device__ __forceinline__ float sigm(float x){ return 1.f/(1.f+expf(-x)); }
__device__ __forceinline__ float lrelu(float x){ return x>0.f? x : 0.01f*x; }

__device__ __forceinline__ void ldm_x4(uint32_t&r0,uint32_t&r1,uint32_t&r2,uint32_t&r3,const void*p){
    uint32_t a=(uint32_t)__cvta_generic_to_shared(p);
    asm volatile("ldmatrix.sync.aligned.m8n8.x4.shared.b16 {%0,%1,%2,%3},[%4];\n"
        :"=r"(r0),"=r"(r1),"=r"(r2),"=r"(r3):"r"(a));
}
__device__ __forceinline__ void ldm_x2(uint32_t&r0,uint32_t&r1,const void*p){
    uint32_t a=(uint32_t)__cvta_generic_to_shared(p);
    asm volatile("ldmatrix.sync.aligned.m8n8.x2.shared.b16 {%0,%1},[%2];\n"
        :"=r"(r0),"=r"(r1):"r"(a));
}
__device__ __forceinline__ void mma_bf16(float*c,const uint32_t*a,const uint32_t*b){
    asm volatile("mma.sync.aligned.m16n8k16.row.col.f32.bf16.bf16.f32 "
        "{%0,%1,%2,%3},{%4,%5,%6,%7},{%8,%9},{%0,%1,%2,%3};\n"
        :"+f"(c[0]),"+f"(c[1]),"+f"(c[2]),"+f"(c[3])
        :"r"(a[0]),"r"(a[1]),"r"(a[2]),"r"(a[3]),"r"(b[0]),"r"(b[1]));
}
__device__ __forceinline__ void cpasync16(void* s, const void* g){
    uint32_t a=(uint32_t)__cvta_generic_to_shared(s);
    asm volatile("cp.async.cg.shared.global [%0],[%1],16;\n"::"r"(a),"l"(g));
}

// ---------------- prep: bf16 casts + gate interleave permutation ----------------
__global__ void prep_kernel(const float*__restrict__ embed,
                            const float*__restrict__ Wih_f,const float*__restrict__ Whh_f,
                            const float*__restrict__ bih_f,const float*__restrict__ bhh_f,
                            const float*__restrict__ Wih_b,const float*__restrict__ Whh_b,
                            const float*__restrict__ bih_b,const float*__restrict__ bhh_b,
                            const float*__restrict__ fc1_w)
{
    int idx = blockIdx.x*blockDim.x + threadIdx.x;
    if (idx < VV*EE) g_embB[idx] = __float2bfloat16(idx < EE ? 0.f : embed[idx]); // row 0 zeroed
    if (idx < 1024*256) {
        int jp = idx>>8, e = idx&255;
        int u = jp>>2, g = jp&3;                 // interleaved col 4u+g  <-  orig row g*256+u
        int src = (g*256+u)*256 + e;
        g_WihB[idx]            = __float2bfloat16(Wih_f[src]);
        g_WihB[1024*256 + idx] = __float2bfloat16(Wih_b[src]);
        g_WhhB[idx]            = __float2bfloat16(Whh_f[src]);
        g_WhhB[1024*256 + idx] = __float2bfloat16(Whh_b[src]);
    }
    if (idx < 512*512) g_fc1B[idx] = __float2bfloat16(fc1_w[idx]);
    if (idx < 1024) {
        int u = idx>>2, g = idx&3; int s = g*256+u;
        g_bias[idx]        = bih_f[s] + bhh_f[s];
        g_bias[1024 + idx] = bih_b[s] + bhh_b[s];
    }
}

// ---------------- pipelined bf16 MMA GEMM core, 3 variants ----------------
// C(M=16384, N) = A(M,K) * B(N,K)^T
// CTA tile 128x128, BK=64, 2-stage cp.async pipeline, 8 warps (warp tile 64x32),
// register double-buffered ldmatrix fragments.
enum { MODE_PROJ = 0, MODE_STEP = 1, MODE_FC1 = 2 };

template<int MODE>
__global__ void __launch_bounds__(256,2)
gemm_kernel(const int*__restrict__ xtok, const float*__restrict__ fc1_b, int kstep)
{
    constexpr int Kdim = (MODE==MODE_FC1) ? 512 : 256;
    constexpr int KT   = Kdim/64;
    const int tileN = blockIdx.x;
    const int n0    = blockIdx.y * 128;
    const int z     = blockIdx.z;               // direction (0 fwd / 1 bwd); 0 for FC1
    const int tid   = threadIdx.x;
    const int warp  = tid>>5, lane = tid&31;
    const int wm    = warp>>2, wn = warp&3;     // 2 x 4 warp grid, warp tile 64x32

    // dynamic smem: As[2][128][72], Bs[2][128][72] bf16
    extern __shared__ __align__(16) __nv_bfloat16 smem[];
    __nv_bfloat16 (*As)[128][72] = (__nv_bfloat16(*)[128][72])smem;
    __nv_bfloat16 (*Bs)[128][72] = (__nv_bfloat16(*)[128][72])(smem + 2*128*72);
    __shared__ int tokS[128];

    const __nv_bfloat16* Bglob;
    if      (MODE==MODE_PROJ) Bglob = g_WihB + (size_t)z*1024*256;
    else if (MODE==MODE_STEP) Bglob = g_WhhB + (size_t)z*1024*256;
    else                      Bglob = g_fc1B;

    const __nv_bfloat16* Abase = nullptr;
    if (MODE==MODE_STEP) Abase = g_h[(kstep+1)&1] + (size_t)z*NPOS*256;
    if (MODE==MODE_FC1)  Abase = g_hcat;

    if (MODE==MODE_PROJ) {
        if (tid < 128) tokS[tid] = xtok[n0 + tid];
        __syncthreads();
    }

    const int nb0 = tileN*128;

    // stage loader: A tile 128x64, B tile 128x64, 16B chunks, 8 cp.async/thread
    auto load_stage = [&](int st, int kt){
        const int k0 = kt*64;
        #pragma unroll
        for (int i=0;i<4;i++) {
            int id = i*256 + tid; int r = id>>3; int c = (id&7)*8;
            const __nv_bfloat16* src;
            if (MODE==MODE_PROJ) src = g_embB + (size_t)tokS[r]*EE + k0 + c;
            else                 src = Abase + (size_t)(n0+r)*Kdim + k0 + c;
            cpasync16(&As[st][r][c], src);
        }
        #pragma unroll
        for (int i=0;i<4;i++) {
            int id = i*256 + tid; int r = id>>3; int c = (id&7)*8;
            cpasync16(&Bs[st][r][c], Bglob + (size_t)(nb0+r)*Kdim + k0 + c);
        }
    };

    float acc[4][4][4];
    #pragma unroll
    for (int a=0;a<4;a++) for (int b=0;b<4;b++) for (int c=0;c<4;c++) acc[a][b][c]=0.f;

    load_stage(0, 0);
    asm volatile("cp.async.commit_group;\n");

    uint32_t afr[2][4][4], bfr[2][4][2];

    auto load_frags = [&](int buf, int st, int kb){
        #pragma unroll
        for (int mi=0;mi<4;mi++)
            ldm_x4(afr[buf][mi][0],afr[buf][mi][1],afr[buf][mi][2],afr[buf][mi][3],
                   &As[st][wm*64 + mi*16 + (lane&15)][kb + (lane>>4)*8]);
        #pragma unroll
        for (int ni=0;ni<4;ni++)
            ldm_x2(bfr[buf][ni][0],bfr[buf][ni][1],
                   &Bs[st][wn*32 + ni*8 + (lane&7)][kb + ((lane>>3)&1)*8]);
    };

    for (int kt = 0; kt < KT; kt++) {
        if (kt+1 < KT) {
            load_stage((kt+1)&1, kt+1);
            asm volatile("cp.async.commit_group;\n");
            asm volatile("cp.async.wait_group 1;\n");
        } else {
            asm volatile("cp.async.wait_group 0;\n");
        }
        __syncthreads();
        const int st = kt&1;
        load_frags(0, st, 0);
        #pragma unroll
        for (int kk=0; kk<4; kk++) {
            const int cur = kk&1;
            if (kk<3) load_frags(cur^1, st, (kk+1)*16);
            #pragma unroll
            for (int mi=0;mi<4;mi++)
                #pragma unroll
                for (int ni=0;ni<4;ni++)
                    mma_bf16(acc[mi][ni], afr[cur][mi], bfr[cur][ni]);
        }
        __syncthreads();
    }

    // ------------- epilogues -------------
    if (MODE==MODE_PROJ) {
        #pragma unroll
        for (int mi=0;mi<4;mi++)
        #pragma unroll
        for (int ni=0;ni<4;ni++) {
            int r = wm*64 + mi*16 + (lane>>2);
            int gcol = tileN*128 + wn*32 + ni*8 + (lane&3)*2;
            __nv_bfloat162 v0, v1;
            v0.x = __float2bfloat16(acc[mi][ni][0]); v0.y = __float2bfloat16(acc[mi][ni][1]);
            v1.x = __float2bfloat16(acc[mi][ni][2]); v1.y = __float2bfloat16(acc[mi][ni][3]);
            *(__nv_bfloat162*)&g_prjB[((size_t)z*NPOS + (n0+r  ))*1024 + gcol] = v0;
            *(__nv_bfloat162*)&g_prjB[((size_t)z*NPOS + (n0+r+8))*1024 + gcol] = v1;
        }
    }
    else if (MODE==MODE_FC1) {
        #pragma unroll
        for (int mi=0;mi<4;mi++)
        #pragma unroll
        for (int ni=0;ni<4;ni++) {
            int r = wm*64 + mi*16 + (lane>>2);
            int c = tileN*128 + wn*32 + ni*8 + (lane&3)*2;
            float b0 = fc1_b[c], b1 = fc1_b[c+1];
            __nv_bfloat162 v0, v1;
            v0.x = __float2bfloat16(lrelu(acc[mi][ni][0] + b0));
            v0.y = __float2bfloat16(lrelu(acc[mi][ni][1] + b1));
            v1.x = __float2bfloat16(lrelu(acc[mi][ni][2] + b0));
            v1.y = __float2bfloat16(lrelu(acc[mi][ni][3] + b1));
            *(__nv_bfloat162*)&g_fc1o[(size_t)(n0+r  )*512 + c] = v0;
            *(__nv_bfloat162*)&g_fc1o[(size_t)(n0+r+8)*512 + c] = v1;
        }
    }
    else { // MODE_STEP: shuffle-fused LSTM update (lane pairs reunite i,f with g,o)
        const __nv_bfloat16* prjZ = g_prjB + (size_t)z*NPOS*1024;
        float*         cZ   = g_c + (size_t)z*NPOS*256;
        __nv_bfloat16* hout = g_h[kstep&1] + (size_t)z*NPOS*256;
        const float*   biasZ = g_bias + z*1024;
        #pragma unroll
        for (int mi=0;mi<4;mi++)
        #pragma unroll
        for (int ni=0;ni<4;ni++) {
            float a0=acc[mi][ni][0], a1=acc[mi][ni][1], a2=acc[mi][ni][2], a3=acc[mi][ni][3];
            float o0=__shfl_xor_sync(0xffffffffu,a0,1);
            float o1=__shfl_xor_sync(0xffffffffu,a1,1);
            float o2=__shfl_xor_sync(0xffffffffu,a2,1);
            float o3=__shfl_xor_sync(0xffffffffu,a3,1);
            if (!(lane&1)) {
                const int gcol = tileN*128 + wn*32 + ni*8 + ((lane&2)?4:0);
                const float4 bv = *(const float4*)&biasZ[gcol];
                const int ucol = gcol>>2;
                #pragma unroll
                for (int hrow=0; hrow<2; hrow++) {
                    const int n = n0 + wm*64 + mi*16 + (lane>>2) + hrow*8;
                    float gi_ = hrow? a2:a0, gf_ = hrow? a3:a1;
                    float gg_ = hrow? o2:o0, go_ = hrow? o3:o1;
                    const int tp = n & (SS-1);
                    const int sp = (z==0) ? (tp + kstep - WSZ) : (tp + WSZ - kstep);
                    const bool valid = (z==0) ? (sp >= 0) : (sp < SS);
                    if (valid) {
                        const int nbr = n + sp - tp;
                        const __nv_bfloat162* pp =
                            (const __nv_bfloat162*)&prjZ[(size_t)nbr*1024 + gcol];
                        float2 p0 = __bfloat1622float2(pp[0]);
                        float2 p1 = __bfloat1622float2(pp[1]);
                        gi_ += p0.x; gf_ += p0.y; gg_ += p1.x; go_ += p1.y;
                    }
                    gi_ += bv.x; gf_ += bv.y; gg_ += bv.z; go_ += bv.w;
                    float i_ = sigm(gi_), f_ = sigm(gf_), g_ = tanhf(gg_), oo = sigm(go_);
                    size_t st = (size_t)n*256 + ucol;
                    float cn = f_*cZ[st] + i_*g_;
                    float hv = oo * tanhf(cn);
                    if (kstep < WSZ) {
                        cZ[st] = cn;
                        hout[st] = __float2bfloat16(hv);
                    } else {
                        // final step: fused concat + leaky straight to g_hcat
                        g_hcat[(size_t)n*512 + (size_t)z*256 + ucol] = __float2bfloat16(lrelu(hv));
                    }
                }
            }
        }
    }
}

// ---------------- step 0: gates = valid?proj:0 + bias ; h=c=0 start ----------------
__global__ void step0_kernel()
{
    int idx = blockIdx.x*blockDim.x + threadIdx.x;   // 2*NPOS*256 units
    int u = idx & 255;
    int n = (idx >> 8) & (NPOS-1);
    int z = idx >> 22;
    int tp = n & (SS-1);
    int sp = (z==0) ? (tp - WSZ) : (tp + WSZ);
    bool valid = (z==0) ? (sp >= 0) : (sp < SS);
    int nbr = n + (sp - tp);
    float4 gv = make_float4(0.f,0.f,0.f,0.f);
    if (valid) {
        const __nv_bfloat162* pp =
            (const __nv_bfloat162*)&g_prjB[((size_t)z*NPOS + nbr)*1024 + u*4];
        float2 p0 = __bfloat1622float2(pp[0]);
        float2 p1 = __bfloat1622float2(pp[1]);
        gv = make_float4(p0.x, p0.y, p1.x, p1.y);
    }
    float4 bv = *(const float4*)&g_bias[(size_t)z*1024 + u*4];
    float gi = sigm(gv.x + bv.x);
    float gg = tanhf(gv.z + bv.z);
    float go = sigm(gv.w + bv.w);
    float c  = gi * gg;                 // f*c0 = 0
    g_c[idx]    = c;
    g_h[0][idx] = __float2bfloat16(go * tanhf(c));
}

// ---------------- fc2 + sigmoid (warp per row) ----------------
__global__ void fc2_kernel(const float*__restrict__ w, const float*__restrict__ b,
                           float*__restrict__ out)
{
    int warp = threadIdx.x >> 5, lane = threadIdx.x & 31;
    int row = blockIdx.x*8 + warp;
    const __nv_bfloat16* a = g_fc1o + (size_t)row*512;
    float s = 0.f;
    #pragma unroll
    for (int i=0;i<16;i++) { int c = lane + i*32; s += __bfloat162float(a[c]) * w[c]; }
    #pragma unroll
    for (int off=16; off; off>>=1) s += __shfl_xor_sync(0xffffffffu, s, off);
    if (lane==0) out[row] = sigm(s + b[0]);
}

// ---------------- launch ----------------
extern "C" void kernel_launch(void* const* d_in, const int* in_sizes, int n_in,
                              void* d_out, int out_size)
{
    const int*   x      = (const int*)  d_in[0];
    const float* embed  = (const float*)d_in[1];
    const float* Wih_f  = (const float*)d_in[2];
    const float* Whh_f  = (const float*)d_in[3];
    const float* bih_f  = (const float*)d_in[4];
    const float* bhh_f  = (const float*)d_in[5];
    const float* Wih_b  = (const float*)d_in[6];
    const float* Whh_b  = (const float*)d_in[7];
    const float* bih_b  = (const float*)d_in[8];
    const float* bhh_b  = (const float*)d_in[9];
    const float* fc1_w  = (const float*)d_in[10];
    const float* fc1_b  = (const float*)d_in[11];
    const float* fc2_w  = (const float*)d_in[12];
    const float* fc2_b  = (const float*)d_in[13];
    float* out = (float*)d_out;

    const int SMEM_GEMM = 2*2*128*72*2;     // 73728 B
    cudaFuncSetAttribute(gemm_kernel<MODE_PROJ>, cudaFuncAttributeMaxDynamicSharedMemorySize, SMEM_GEMM);
    cudaFuncSetAttribute(gemm_kernel<MODE_STEP>, cudaFuncAttributeMaxDynamicSharedMemorySize, SMEM_GEMM);
    cudaFuncSetAttribute(gemm_kernel<MODE_FC1>,  cudaFuncAttributeMaxDynamicSharedMemorySize, SMEM_GEMM);

    prep_kernel<<<(VV*EE + 255)/256, 256>>>(embed, Wih_f, Whh_f, bih_f, bhh_f,
                                            Wih_b, Whh_b, bih_b, bhh_b, fc1_w);

    gemm_kernel<MODE_PROJ><<<dim3(8, NPOS/128, 2), 256, SMEM_GEMM>>>(x, nullptr, 0);

    step0_kernel<<<(2*NPOS*256)/256, 256>>>();

    for (int k = 1; k <= WSZ; k++)
        gemm_kernel<MODE_STEP><<<dim3(8, NPOS/128, 2), 256, SMEM_GEMM>>>(nullptr, nullptr, k);

    gemm_kernel<MODE_FC1><<<dim3(4, NPOS/128, 1), 256, SMEM_GEMM>>>(nullptr, fc1_b, 0);

    fc2_kernel<<<NPOS/8, 256>>>(fc2_w, fc2_b, out);
}